// round 2
// baseline (speedup 1.0000x reference)
#include <cuda_runtime.h>
#include <math.h>

// ---------------------------------------------------------------------------
// InteractionBlock (SchNet): 
//   g   = exp(coeff*(e - offsets)^2)            [E,64]
//   W   = g @ Wf2 + bf2                         [E,128]   <-- replaced by LUT(e)
//   rf  = r @ Wa                                [N,128]
//   y   = segment_sum(rf[src] * W, dst)         [N,128]
//   y   = ssp(y @ W1 + b1) @ W2 + b2            [N,128]
// ---------------------------------------------------------------------------

#define NF 128
#define N_GAUSS 64
#define TAB 5121                 // table rows; step = 5/5120 = 1/1024
#define MAX_N 50048              // padded capacity for node buffers

static __device__ float g_rf  [MAX_N * NF];
static __device__ float g_acc [MAX_N * NF];
static __device__ float g_h   [MAX_N * NF];
static __device__ float g_table[TAB * NF];

__device__ __forceinline__ float ssp(float x) {
    // shifted softplus: log(1+e^x) - log(2), numerically stable
    float ax = fabsf(x);
    float sp = fmaxf(x, 0.0f) + log1pf(__expf(-ax));
    return sp - 0.69314718055994530942f;
}

// ---------------------------------------------------------------------------
// Table build: table[i][f] = bf2[f] + sum_k exp(coeff*(i*h - o_k)^2) * Wf2[k][f]
// ---------------------------------------------------------------------------
__global__ void build_table_kernel(const float* __restrict__ Wf2,
                                   const float* __restrict__ bf2) {
    const float WIDTH = 5.0f / 63.0f;
    const float COEFF = -0.5f / (WIDTH * WIDTH);
    const float HSTEP = 1.0f / 1024.0f;

    int f = threadIdx.x;        // 0..127
    int i = blockIdx.x;         // 0..TAB-1
    float ev = (float)i * HSTEP;
    float acc = bf2[f];
#pragma unroll
    for (int k = 0; k < N_GAUSS; k++) {
        float d = ev - (float)k * WIDTH;
        acc += __expf(COEFF * d * d) * Wf2[k * NF + f];
    }
    g_table[i * NF + f] = acc;
}

// ---------------------------------------------------------------------------
// Zero the scatter accumulator
// ---------------------------------------------------------------------------
__global__ void zero_acc_kernel(int n4) {
    int i = blockIdx.x * blockDim.x + threadIdx.x;
    if (i < n4) ((float4*)g_acc)[i] = make_float4(0.f, 0.f, 0.f, 0.f);
}

// ---------------------------------------------------------------------------
// Edge kernel: one warp per edge.
//   W(e) via linear interp of g_table; v = rf[src]*W; red.v4 into g_acc[dst].
// ---------------------------------------------------------------------------
__global__ void edge_kernel(const float* __restrict__ e,
                            const int2*  __restrict__ a,   // (dst, src)
                            int E) {
    int gid  = blockIdx.x * blockDim.x + threadIdx.x;
    int edge = gid >> 5;
    int lane = threadIdx.x & 31;
    if (edge >= E) return;

    float ev = e[edge];          // broadcast within warp (same address)
    int2  pr = a[edge];          // pr.x = dst, pr.y = src

    float u = ev * 1024.0f;      // (TAB-1)/5
    int   i = (int)u;
    i = max(0, min(i, TAB - 2));
    float fr = u - (float)i;

    const float4* t0 = (const float4*)(g_table + (size_t)i * NF);
    const float4* t1 = (const float4*)(g_table + (size_t)(i + 1) * NF);
    float4 w0 = t0[lane];
    float4 w1 = t1[lane];

    const float4* rp = (const float4*)(g_rf + (size_t)pr.y * NF);
    float4 rv = rp[lane];

    float4 v;
    v.x = rv.x * fmaf(fr, w1.x - w0.x, w0.x);
    v.y = rv.y * fmaf(fr, w1.y - w0.y, w0.y);
    v.z = rv.z * fmaf(fr, w1.z - w0.z, w0.z);
    v.w = rv.w * fmaf(fr, w1.w - w0.w, w0.w);

    float* dp = g_acc + (size_t)pr.x * NF + lane * 4;
    asm volatile("red.global.add.v4.f32 [%0], {%1, %2, %3, %4};"
                 :: "l"(dp), "f"(v.x), "f"(v.y), "f"(v.z), "f"(v.w)
                 : "memory");
}

// ---------------------------------------------------------------------------
// SGEMM: C[N,128] = act(A[N,128] @ B[128,128] (+ bias))
// Block: 256 threads, tile 64 rows x 128 cols, BK=32, thread microtile 8x4.
// ---------------------------------------------------------------------------
template <int ACT, bool HAS_BIAS>
__global__ void gemm128_kernel(const float* __restrict__ A,
                               const float* __restrict__ B,
                               const float* __restrict__ bias,
                               float* __restrict__ C, int N) {
    __shared__ float As[64][32];
    __shared__ float Bs[32][128];

    int tid = threadIdx.x;
    int tx  = tid & 31;      // column group: cols tx*4..tx*4+3
    int ty  = tid >> 5;      // row group: rows ty*8..ty*8+7
    int rowBase = blockIdx.x * 64;

    float4 acc[8];
#pragma unroll
    for (int i = 0; i < 8; i++) acc[i] = make_float4(0.f, 0.f, 0.f, 0.f);

#pragma unroll
    for (int kt = 0; kt < 4; kt++) {
        // Load A tile: 64x32 floats = 512 float4; 2 per thread.
#pragma unroll
        for (int j = 0; j < 2; j++) {
            int idx = tid + j * 256;          // 0..511
            int ar  = idx >> 3;               // 0..63
            int ac4 = idx & 7;                // 0..7
            int grow = rowBase + ar;
            float4 av = make_float4(0.f, 0.f, 0.f, 0.f);
            if (grow < N)
                av = *(const float4*)(A + (size_t)grow * NF + kt * 32 + ac4 * 4);
            *(float4*)&As[ar][ac4 * 4] = av;
        }
        // Load B tile: 32x128 floats = 1024 float4; 4 per thread.
#pragma unroll
        for (int j = 0; j < 4; j++) {
            int idx = tid + j * 256;          // 0..1023
            int br  = idx >> 5;               // 0..31
            int bc4 = idx & 31;               // 0..31
            float4 bv = *(const float4*)(B + (size_t)(kt * 32 + br) * NF + bc4 * 4);
            *(float4*)&Bs[br][bc4 * 4] = bv;
        }
        __syncthreads();

#pragma unroll
        for (int k = 0; k < 32; k++) {
            float4 bv = *(const float4*)&Bs[k][tx * 4];
#pragma unroll
            for (int i = 0; i < 8; i++) {
                float av = As[ty * 8 + i][k];
                acc[i].x = fmaf(av, bv.x, acc[i].x);
                acc[i].y = fmaf(av, bv.y, acc[i].y);
                acc[i].z = fmaf(av, bv.z, acc[i].z);
                acc[i].w = fmaf(av, bv.w, acc[i].w);
            }
        }
        __syncthreads();
    }

    float4 bb = make_float4(0.f, 0.f, 0.f, 0.f);
    if (HAS_BIAS) bb = *(const float4*)(bias + tx * 4);

#pragma unroll
    for (int i = 0; i < 8; i++) {
        int row = rowBase + ty * 8 + i;
        if (row < N) {
            float4 o;
            o.x = acc[i].x + bb.x;
            o.y = acc[i].y + bb.y;
            o.z = acc[i].z + bb.z;
            o.w = acc[i].w + bb.w;
            if (ACT == 1) { o.x = ssp(o.x); o.y = ssp(o.y); o.z = ssp(o.z); o.w = ssp(o.w); }
            *(float4*)(C + (size_t)row * NF + tx * 4) = o;
        }
    }
}

// ---------------------------------------------------------------------------
// Launch
// ---------------------------------------------------------------------------
extern "C" void kernel_launch(void* const* d_in, const int* in_sizes, int n_in,
                              void* d_out, int out_size) {
    const float* r   = (const float*)d_in[0];
    const float* e   = (const float*)d_in[1];
    const float* Wf2 = (const float*)d_in[2];
    const float* bf2 = (const float*)d_in[3];
    const float* Wa  = (const float*)d_in[4];
    const float* W1  = (const float*)d_in[5];
    const float* b1  = (const float*)d_in[6];
    const float* W2  = (const float*)d_in[7];
    const float* b2  = (const float*)d_in[8];
    const int*   a   = (const int*)d_in[9];

    int N = in_sizes[0] / NF;     // 50000
    int E = in_sizes[1];          // 800000

    float *p_rf, *p_acc, *p_h;
    cudaGetSymbolAddress((void**)&p_rf,  g_rf);
    cudaGetSymbolAddress((void**)&p_acc, g_acc);
    cudaGetSymbolAddress((void**)&p_h,   g_h);

    // 1. Filter lookup table (includes bf2 bias)
    build_table_kernel<<<TAB, 128>>>(Wf2, bf2);

    // 2. Zero scatter accumulator
    int n4 = (N * NF) / 4;
    zero_acc_kernel<<<(n4 + 255) / 256, 256>>>(n4);

    // 3. rf = r @ Wa   (no bias, no act)
    int gb = (N + 63) / 64;
    gemm128_kernel<0, false><<<gb, 256>>>(r, Wa, nullptr, p_rf, N);

    // 4. Edge gather-modulate-scatter (warp per edge)
    int eblocks = (E + 7) / 8;    // 8 warps per 256-thread block
    edge_kernel<<<eblocks, 256>>>(e, (const int2*)a, E);

    // 5. h = ssp(acc @ W1 + b1)
    gemm128_kernel<1, true><<<gb, 256>>>(p_acc, W1, b1, p_h, N);

    // 6. out = h @ W2 + b2
    gemm128_kernel<0, true><<<gb, 256>>>(p_h, W2, b2, (float*)d_out, N);
}